// round 2
// baseline (speedup 1.0000x reference)
#include <cuda_runtime.h>
#include <cstdint>

#define NB 2
#define NNODES 5000
#define NEDGES 160000
#define FIN 128
#define HID 128
#define ED 16
#define INE 288          // 2*FIN + 16 + ED
#define EPB 16           // edges per block (NEDGES % EPB == 0)
#define NPB 8            // nodes per block (NNODES % NPB == 0)

// Scratch (allocation-free): per-batch aggregates + per-node edge counts.
__device__ float g_agg_h[NB * NNODES * HID];   // segment_sum(ef, row)
__device__ float g_agg_c[NB * NNODES * 12];    // segment_sum(trans, row)
__device__ float g_cnt[NNODES];                // edge count per node (row is batch-independent)

__global__ void zero_kernel() {
    const int T1 = NB * NNODES * HID;
    const int T2 = T1 + NB * NNODES * 12;
    const int total = T2 + NNODES;
    for (int i = blockIdx.x * blockDim.x + threadIdx.x; i < total;
         i += gridDim.x * blockDim.x) {
        if (i < T1)       g_agg_h[i] = 0.0f;
        else if (i < T2)  g_agg_c[i - T1] = 0.0f;
        else              g_cnt[i - T2] = 0.0f;
    }
}

__global__ void count_kernel(const int* __restrict__ edge_index) {
    int e = blockIdx.x * blockDim.x + threadIdx.x;
    if (e < NEDGES) atomicAdd(&g_cnt[edge_index[e]], 1.0f);
}

// Fused per-edge pipeline: gather -> radial -> edge MLP -> coord MLP -> scatter.
__global__ __launch_bounds__(128) void edge_kernel(
    const float* __restrict__ h, const float* __restrict__ coord,
    const int* __restrict__ edge_index, const float* __restrict__ edge_attr,
    const float* __restrict__ W_e1, const float* __restrict__ b_e1,
    const float* __restrict__ W_e2, const float* __restrict__ b_e2,
    const float* __restrict__ W_c1, const float* __restrict__ b_c1,
    const float* __restrict__ W_c2)
{
    __shared__ float xs[EPB][INE];    // [h_row | h_col | radial | edge_attr]
    __shared__ float h1s[EPB][HID];   // hidden buffer (reused)
    __shared__ float efs[EPB][HID];   // edge features
    __shared__ float cds[EPB][12];    // coord diff
    __shared__ float ws[EPB][4];      // coord weights
    __shared__ int   rows_s[EPB], cols_s[EPB];

    const int t  = threadIdx.x;
    const int e0 = blockIdx.x * EPB;
    const int b  = blockIdx.y;
    const float* hb = h + (size_t)b * NNODES * FIN;
    const float* cb = coord + (size_t)b * NNODES * 12;

    if (t < EPB) {
        rows_s[t] = edge_index[e0 + t];
        cols_s[t] = edge_index[NEDGES + e0 + t];
    }
    __syncthreads();

    // Gather h[row], h[col] (coalesced 128-float rows, L2-resident)
    #pragma unroll
    for (int e = 0; e < EPB; e++) {
        xs[e][t]       = hb[rows_s[e] * FIN + t];
        xs[e][FIN + t] = hb[cols_s[e] * FIN + t];
    }
    // edge_attr (EPB*ED = 256 elems)
    for (int i = t; i < EPB * ED; i += 128) {
        int e = i / ED, c = i % ED;
        xs[e][2 * FIN + 16 + c] = edge_attr[(size_t)(e0 + e) * ED + c];
    }
    // coord diff (EPB*12 = 192 elems)
    for (int i = t; i < EPB * 12; i += 128) {
        int e = i / 12, c = i % 12;
        cds[e][c] = cb[rows_s[e] * 12 + c] - cb[cols_s[e] * 12 + c];
    }
    __syncthreads();

    // radial: prod = cd cd^T (16), F.normalize over the 16 entries
    if (t < EPB) {
        float cd[12];
        #pragma unroll
        for (int c = 0; c < 12; c++) cd[c] = cds[t][c];
        float prod[16];
        float ss = 0.0f;
        #pragma unroll
        for (int j = 0; j < 4; j++)
            #pragma unroll
            for (int k = 0; k < 4; k++) {
                float p = cd[j*3]*cd[k*3] + cd[j*3+1]*cd[k*3+1] + cd[j*3+2]*cd[k*3+2];
                prod[j * 4 + k] = p;
                ss += p * p;
            }
        float inv = 1.0f / fmaxf(sqrtf(ss), 1e-12f);
        #pragma unroll
        for (int i = 0; i < 16; i++) xs[t][2 * FIN + i] = prod[i] * inv;
    }
    __syncthreads();

    float acc[EPB];

    // GEMM1: x[288] @ W_e1 -> relu -> h1s
    {
        float bj = b_e1[t];
        #pragma unroll
        for (int e = 0; e < EPB; e++) acc[e] = bj;
        for (int k = 0; k < INE; k += 4) {
            float w0 = W_e1[(k + 0) * HID + t];
            float w1 = W_e1[(k + 1) * HID + t];
            float w2 = W_e1[(k + 2) * HID + t];
            float w3 = W_e1[(k + 3) * HID + t];
            #pragma unroll
            for (int e = 0; e < EPB; e++) {
                float4 x4 = *(const float4*)&xs[e][k];
                acc[e] = fmaf(x4.x, w0, fmaf(x4.y, w1, fmaf(x4.z, w2, fmaf(x4.w, w3, acc[e]))));
            }
        }
        #pragma unroll
        for (int e = 0; e < EPB; e++) h1s[e][t] = fmaxf(acc[e], 0.0f);
    }
    __syncthreads();

    // GEMM2: h1 @ W_e2 -> relu -> efs (edge features)
    {
        float bj = b_e2[t];
        #pragma unroll
        for (int e = 0; e < EPB; e++) acc[e] = bj;
        for (int k = 0; k < HID; k += 4) {
            float w0 = W_e2[(k + 0) * HID + t];
            float w1 = W_e2[(k + 1) * HID + t];
            float w2 = W_e2[(k + 2) * HID + t];
            float w3 = W_e2[(k + 3) * HID + t];
            #pragma unroll
            for (int e = 0; e < EPB; e++) {
                float4 x4 = *(const float4*)&h1s[e][k];
                acc[e] = fmaf(x4.x, w0, fmaf(x4.y, w1, fmaf(x4.z, w2, fmaf(x4.w, w3, acc[e]))));
            }
        }
        #pragma unroll
        for (int e = 0; e < EPB; e++) efs[e][t] = fmaxf(acc[e], 0.0f);
    }
    __syncthreads();

    // GEMM3: ef @ W_c1 -> relu -> h1s (reuse)
    {
        float bj = b_c1[t];
        #pragma unroll
        for (int e = 0; e < EPB; e++) acc[e] = bj;
        for (int k = 0; k < HID; k += 4) {
            float w0 = W_c1[(k + 0) * HID + t];
            float w1 = W_c1[(k + 1) * HID + t];
            float w2 = W_c1[(k + 2) * HID + t];
            float w3 = W_c1[(k + 3) * HID + t];
            #pragma unroll
            for (int e = 0; e < EPB; e++) {
                float4 x4 = *(const float4*)&efs[e][k];
                acc[e] = fmaf(x4.x, w0, fmaf(x4.y, w1, fmaf(x4.z, w2, fmaf(x4.w, w3, acc[e]))));
            }
        }
        #pragma unroll
        for (int e = 0; e < EPB; e++) h1s[e][t] = fmaxf(acc[e], 0.0f);
    }
    __syncthreads();

    // GEMM4: h2 @ W_c2 -> w[4] (no bias, no relu). EPB*4 = 64 dot products.
    if (t < EPB * 4) {
        int e = t >> 2, c = t & 3;
        float a = 0.0f;
        #pragma unroll 4
        for (int k = 0; k < HID; k++) a = fmaf(h1s[e][k], W_c2[k * 4 + c], a);
        ws[e][c] = a;
    }
    __syncthreads();

    // Scatter: agg_h += ef ; agg_c += cd * w
    float* aggh = g_agg_h + (size_t)b * NNODES * HID;
    #pragma unroll
    for (int e = 0; e < EPB; e++)
        atomicAdd(&aggh[rows_s[e] * HID + t], efs[e][t]);

    float* aggc = g_agg_c + (size_t)b * NNODES * 12;
    for (int i = t; i < EPB * 12; i += 128) {
        int e = i / 12, c = i % 12;
        atomicAdd(&aggc[rows_s[e] * 12 + c], cds[e][c] * ws[e][c / 3]);
    }
}

// Node MLP (residual) + coord update. Writes final outputs.
__global__ __launch_bounds__(128) void node_kernel(
    const float* __restrict__ h, const float* __restrict__ coord,
    const float* __restrict__ W_n1, const float* __restrict__ b_n1,
    const float* __restrict__ W_n2, const float* __restrict__ b_n2,
    float* __restrict__ out)
{
    __shared__ float zs[NPB][2 * FIN];   // [h | agg_h]
    __shared__ float h1s[NPB][HID];

    const int t  = threadIdx.x;
    const int n0 = blockIdx.x * NPB;
    const int b  = blockIdx.y;
    const float* hb   = h + (size_t)b * NNODES * FIN;
    const float* aggh = g_agg_h + (size_t)b * NNODES * HID;

    #pragma unroll
    for (int e = 0; e < NPB; e++) {
        zs[e][t]       = hb[(n0 + e) * FIN + t];
        zs[e][FIN + t] = aggh[(n0 + e) * HID + t];
    }
    __syncthreads();

    float acc[NPB];
    {
        float bj = b_n1[t];
        #pragma unroll
        for (int e = 0; e < NPB; e++) acc[e] = bj;
        for (int k = 0; k < 2 * FIN; k += 4) {
            float w0 = W_n1[(k + 0) * HID + t];
            float w1 = W_n1[(k + 1) * HID + t];
            float w2 = W_n1[(k + 2) * HID + t];
            float w3 = W_n1[(k + 3) * HID + t];
            #pragma unroll
            for (int e = 0; e < NPB; e++) {
                float4 x4 = *(const float4*)&zs[e][k];
                acc[e] = fmaf(x4.x, w0, fmaf(x4.y, w1, fmaf(x4.z, w2, fmaf(x4.w, w3, acc[e]))));
            }
        }
        #pragma unroll
        for (int e = 0; e < NPB; e++) h1s[e][t] = fmaxf(acc[e], 0.0f);
    }
    __syncthreads();
    {
        float bj = b_n2[t];
        #pragma unroll
        for (int e = 0; e < NPB; e++) acc[e] = bj;
        for (int k = 0; k < HID; k += 4) {
            float w0 = W_n2[(k + 0) * FIN + t];
            float w1 = W_n2[(k + 1) * FIN + t];
            float w2 = W_n2[(k + 2) * FIN + t];
            float w3 = W_n2[(k + 3) * FIN + t];
            #pragma unroll
            for (int e = 0; e < NPB; e++) {
                float4 x4 = *(const float4*)&h1s[e][k];
                acc[e] = fmaf(x4.x, w0, fmaf(x4.y, w1, fmaf(x4.z, w2, fmaf(x4.w, w3, acc[e]))));
            }
        }
    }

    // h_new = h + mlp(z)   (zs[e][t] still holds h)
    float* outh = out + (size_t)b * NNODES * FIN;
    #pragma unroll
    for (int e = 0; e < NPB; e++)
        outh[(n0 + e) * FIN + t] = zs[e][t] + acc[e];

    // coord_new = coord + agg_c / max(cnt, 1)
    float* outc = out + (size_t)NB * NNODES * FIN + (size_t)b * NNODES * 12;
    const float* cb   = coord + (size_t)b * NNODES * 12;
    const float* aggc = g_agg_c + (size_t)b * NNODES * 12;
    for (int i = t; i < NPB * 12; i += 128) {
        int e = i / 12, c = i % 12;
        int n = n0 + e;
        float cnt = fmaxf(g_cnt[n], 1.0f);
        outc[n * 12 + c] = cb[n * 12 + c] + aggc[n * 12 + c] / cnt;
    }
}

extern "C" void kernel_launch(void* const* d_in, const int* in_sizes, int n_in,
                              void* d_out, int out_size)
{
    const float* h         = (const float*)d_in[0];
    const float* coord     = (const float*)d_in[1];
    const int*   edge_index= (const int*)  d_in[2];
    const float* edge_attr = (const float*)d_in[3];
    const float* W_e1 = (const float*)d_in[4];
    const float* b_e1 = (const float*)d_in[5];
    const float* W_e2 = (const float*)d_in[6];
    const float* b_e2 = (const float*)d_in[7];
    const float* W_n1 = (const float*)d_in[8];
    const float* b_n1 = (const float*)d_in[9];
    const float* W_n2 = (const float*)d_in[10];
    const float* b_n2 = (const float*)d_in[11];
    const float* W_c1 = (const float*)d_in[12];
    const float* b_c1 = (const float*)d_in[13];
    const float* W_c2 = (const float*)d_in[14];
    float* out = (float*)d_out;

    zero_kernel<<<1024, 256>>>();
    count_kernel<<<(NEDGES + 255) / 256, 256>>>(edge_index);
    edge_kernel<<<dim3(NEDGES / EPB, NB), 128>>>(
        h, coord, edge_index, edge_attr,
        W_e1, b_e1, W_e2, b_e2, W_c1, b_c1, W_c2);
    node_kernel<<<dim3(NNODES / NPB, NB), 128>>>(
        h, coord, W_n1, b_n1, W_n2, b_n2, out);
}

// round 4
// speedup vs baseline: 1.0451x; 1.0451x over previous
#include <cuda_runtime.h>
#include <cstdint>

#define NB 2
#define NNODES 5000
#define NEDGES 160000
#define FIN 128
#define HID 128
#define ED 16
#define INE 288          // 2*FIN + 16 + ED
#define EPB 32           // edges per block
#define XS 36            // padded row stride (floats): 144B -> 16B aligned, 4-way max bank conflict
#define NPB 8            // nodes per block

// Packed fp32x2 helpers (sm_100+)
#define FMA2(acc, a, b) asm("fma.rn.f32x2 %0, %1, %2, %0;" : "+l"(acc) : "l"(a), "l"(b))
#define PACK2(d, x)     asm("mov.b64 %0, {%1, %1};" : "=l"(d) : "f"(x))
#define UNPK(lo, hi, v) asm("mov.b64 {%0, %1}, %2;" : "=f"(lo), "=f"(hi) : "l"(v))

// Scratch (allocation-free)
__device__ float g_agg_h[NB * NNODES * HID];
__device__ float g_agg_c[NB * NNODES * 12];
__device__ float g_cnt[NNODES];

// Dynamic smem layout (floats):
//   xsT  [INE][XS]   transposed input features  (aliased by efT after GEMM1)
//   h1T  [HID][XS]   hidden buffer
//   cds  [EPB][12]
//   ws   [EPB][4]
//   rows_s / cols_s  [EPB] ints
#define OFF_XST  0
#define OFF_H1T  (INE * XS)
#define OFF_CDS  (OFF_H1T + HID * XS)
#define OFF_WS   (OFF_CDS + EPB * 12)
#define OFF_IDX  (OFF_WS + EPB * 4)
#define SMEM_FLOATS (OFF_IDX + 2 * EPB)
#define SMEM_BYTES  (SMEM_FLOATS * 4)

__global__ void zero_kernel() {
    const int T1 = NB * NNODES * HID;
    const int T2 = T1 + NB * NNODES * 12;
    const int total = T2 + NNODES;
    for (int i = blockIdx.x * blockDim.x + threadIdx.x; i < total;
         i += gridDim.x * blockDim.x) {
        if (i < T1)       g_agg_h[i] = 0.0f;
        else if (i < T2)  g_agg_c[i - T1] = 0.0f;
        else              g_cnt[i - T2] = 0.0f;
    }
}

__global__ void count_kernel(const int* __restrict__ edge_index) {
    int e = blockIdx.x * blockDim.x + threadIdx.x;
    if (e < NEDGES) atomicAdd(&g_cnt[edge_index[e]], 1.0f);
}

// Packed-f32x2 GEMM over EPB edges. inT/outT transposed [K][XS] / [HID][XS].
// Each thread owns output channel t; accumulates EPB edges in 16 f32x2 pairs.
template<int K>
__device__ __forceinline__ void gemm_pack_relu(
    const float* __restrict__ W, const float* __restrict__ bias,
    const float* __restrict__ inT, float* __restrict__ outT, int t)
{
    uint64_t acc[EPB / 2];
    float bj = bias[t];
    uint64_t bj2; PACK2(bj2, bj);
    #pragma unroll
    for (int p = 0; p < EPB / 2; p++) acc[p] = bj2;

    #pragma unroll 4
    for (int k = 0; k < K; k++) {
        float w = W[k * HID + t];
        uint64_t w2; PACK2(w2, w);
        const ulonglong2* xr = (const ulonglong2*)(inT + k * XS);
        #pragma unroll
        for (int q = 0; q < EPB / 4; q++) {
            ulonglong2 v = xr[q];            // 4 edges (2 f32x2 pairs), broadcast LDS.128
            FMA2(acc[2 * q],     v.x, w2);
            FMA2(acc[2 * q + 1], v.y, w2);
        }
    }
    #pragma unroll
    for (int p = 0; p < EPB / 2; p++) {
        float lo, hi; UNPK(lo, hi, acc[p]);
        outT[t * XS + 2 * p]     = fmaxf(lo, 0.0f);
        outT[t * XS + 2 * p + 1] = fmaxf(hi, 0.0f);
    }
}

__global__ __launch_bounds__(128) void edge_kernel(
    const float* __restrict__ h, const float* __restrict__ coord,
    const int* __restrict__ edge_index, const float* __restrict__ edge_attr,
    const float* __restrict__ W_e1, const float* __restrict__ b_e1,
    const float* __restrict__ W_e2, const float* __restrict__ b_e2,
    const float* __restrict__ W_c1, const float* __restrict__ b_c1,
    const float* __restrict__ W_c2)
{
    extern __shared__ float sm[];
    float* xsT  = sm + OFF_XST;
    float* h1T  = sm + OFF_H1T;
    float* efT  = xsT;                     // alias: xsT dead after GEMM1
    float* cds  = sm + OFF_CDS;
    float* wsS  = sm + OFF_WS;
    int*   rows_s = (int*)(sm + OFF_IDX);
    int*   cols_s = rows_s + EPB;

    const int t  = threadIdx.x;
    const int e0 = blockIdx.x * EPB;
    const int b  = blockIdx.y;
    const float* hb = h + (size_t)b * NNODES * FIN;
    const float* cb = coord + (size_t)b * NNODES * 12;

    if (t < EPB) {
        rows_s[t] = edge_index[e0 + t];
        cols_s[t] = edge_index[NEDGES + e0 + t];
    }
    __syncthreads();

    // Gather h[row], h[col] into transposed layout: xsT[feature][edge]
    #pragma unroll
    for (int e = 0; e < EPB; e++) {
        xsT[t * XS + e]         = hb[rows_s[e] * FIN + t];
        xsT[(FIN + t) * XS + e] = hb[cols_s[e] * FIN + t];
    }
    // edge_attr -> xsT rows [272..288)
    for (int i = t; i < EPB * ED; i += 128) {
        int e = i >> 4, c = i & 15;
        xsT[(2 * FIN + 16 + c) * XS + e] = edge_attr[(size_t)(e0 + e) * ED + c];
    }
    // coord diff
    for (int i = t; i < EPB * 12; i += 128) {
        int e = i / 12, c = i % 12;
        cds[e * 12 + c] = cb[rows_s[e] * 12 + c] - cb[cols_s[e] * 12 + c];
    }
    __syncthreads();

    // radial -> xsT rows [256..272)
    if (t < EPB) {
        float cd[12];
        #pragma unroll
        for (int c = 0; c < 12; c++) cd[c] = cds[t * 12 + c];
        float prod[16];
        float ss = 0.0f;
        #pragma unroll
        for (int j = 0; j < 4; j++)
            #pragma unroll
            for (int k = 0; k < 4; k++) {
                float p = cd[j*3]*cd[k*3] + cd[j*3+1]*cd[k*3+1] + cd[j*3+2]*cd[k*3+2];
                prod[j * 4 + k] = p;
                ss += p * p;
            }
        float inv = 1.0f / fmaxf(sqrtf(ss), 1e-12f);
        #pragma unroll
        for (int i = 0; i < 16; i++) xsT[(2 * FIN + i) * XS + t] = prod[i] * inv;
    }
    __syncthreads();

    // GEMM1: xsT[288] -> relu -> h1T
    gemm_pack_relu<INE>(W_e1, b_e1, xsT, h1T, t);
    __syncthreads();
    // GEMM2: h1T -> relu -> efT (edge features; aliases xsT, now dead)
    gemm_pack_relu<HID>(W_e2, b_e2, h1T, efT, t);
    __syncthreads();
    // GEMM3: efT -> relu -> h1T (coord hidden; h1 dead)
    gemm_pack_relu<HID>(W_c1, b_c1, efT, h1T, t);
    __syncthreads();

    // GEMM4: h2 @ W_c2 -> w[4]. 128 threads = 4 outputs x 32 edges.
    {
        int c = t >> 5, e = t & 31;
        float a = 0.0f;
        #pragma unroll 8
        for (int k = 0; k < HID; k++) a = fmaf(h1T[k * XS + e], W_c2[k * 4 + c], a);
        wsS[e * 4 + c] = a;
    }
    __syncthreads();

    // Scatter: agg_h += ef ; agg_c += cd * w
    float* aggh = g_agg_h + (size_t)b * NNODES * HID;
    #pragma unroll
    for (int e = 0; e < EPB; e++)
        atomicAdd(&aggh[rows_s[e] * HID + t], efT[t * XS + e]);

    float* aggc = g_agg_c + (size_t)b * NNODES * 12;
    for (int i = t; i < EPB * 12; i += 128) {
        int e = i / 12, c = i % 12;
        atomicAdd(&aggc[rows_s[e] * 12 + c], cds[e * 12 + c] * wsS[e * 4 + c / 3]);
    }
}

// Node MLP (residual) + coord update.
__global__ __launch_bounds__(128) void node_kernel(
    const float* __restrict__ h, const float* __restrict__ coord,
    const float* __restrict__ W_n1, const float* __restrict__ b_n1,
    const float* __restrict__ W_n2, const float* __restrict__ b_n2,
    float* __restrict__ out)
{
    __shared__ float zs[NPB][2 * FIN];
    __shared__ float h1s[NPB][HID];

    const int t  = threadIdx.x;
    const int n0 = blockIdx.x * NPB;
    const int b  = blockIdx.y;
    const float* hb   = h + (size_t)b * NNODES * FIN;
    const float* aggh = g_agg_h + (size_t)b * NNODES * HID;

    #pragma unroll
    for (int e = 0; e < NPB; e++) {
        zs[e][t]       = hb[(n0 + e) * FIN + t];
        zs[e][FIN + t] = aggh[(n0 + e) * HID + t];
    }
    __syncthreads();

    float acc[NPB];
    {
        float bj = b_n1[t];
        #pragma unroll
        for (int e = 0; e < NPB; e++) acc[e] = bj;
        for (int k = 0; k < 2 * FIN; k += 4) {
            float w0 = W_n1[(k + 0) * HID + t];
            float w1 = W_n1[(k + 1) * HID + t];
            float w2 = W_n1[(k + 2) * HID + t];
            float w3 = W_n1[(k + 3) * HID + t];
            #pragma unroll
            for (int e = 0; e < NPB; e++) {
                float4 x4 = *(const float4*)&zs[e][k];
                acc[e] = fmaf(x4.x, w0, fmaf(x4.y, w1, fmaf(x4.z, w2, fmaf(x4.w, w3, acc[e]))));
            }
        }
        #pragma unroll
        for (int e = 0; e < NPB; e++) h1s[e][t] = fmaxf(acc[e], 0.0f);
    }
    __syncthreads();
    {
        float bj = b_n2[t];
        #pragma unroll
        for (int e = 0; e < NPB; e++) acc[e] = bj;
        for (int k = 0; k < HID; k += 4) {
            float w0 = W_n2[(k + 0) * FIN + t];
            float w1 = W_n2[(k + 1) * FIN + t];
            float w2 = W_n2[(k + 2) * FIN + t];
            float w3 = W_n2[(k + 3) * FIN + t];
            #pragma unroll
            for (int e = 0; e < NPB; e++) {
                float4 x4 = *(const float4*)&h1s[e][k];
                acc[e] = fmaf(x4.x, w0, fmaf(x4.y, w1, fmaf(x4.z, w2, fmaf(x4.w, w3, acc[e]))));
            }
        }
    }

    float* outh = out + (size_t)b * NNODES * FIN;
    #pragma unroll
    for (int e = 0; e < NPB; e++)
        outh[(n0 + e) * FIN + t] = zs[e][t] + acc[e];

    float* outc = out + (size_t)NB * NNODES * FIN + (size_t)b * NNODES * 12;
    const float* cb   = coord + (size_t)b * NNODES * 12;
    const float* aggc = g_agg_c + (size_t)b * NNODES * 12;
    for (int i = t; i < NPB * 12; i += 128) {
        int e = i / 12, c = i % 12;
        int n = n0 + e;
        float cnt = fmaxf(g_cnt[n], 1.0f);
        outc[n * 12 + c] = cb[n * 12 + c] + aggc[n * 12 + c] / cnt;
    }
}

extern "C" void kernel_launch(void* const* d_in, const int* in_sizes, int n_in,
                              void* d_out, int out_size)
{
    const float* h         = (const float*)d_in[0];
    const float* coord     = (const float*)d_in[1];
    const int*   edge_index= (const int*)  d_in[2];
    const float* edge_attr = (const float*)d_in[3];
    const float* W_e1 = (const float*)d_in[4];
    const float* b_e1 = (const float*)d_in[5];
    const float* W_e2 = (const float*)d_in[6];
    const float* b_e2 = (const float*)d_in[7];
    const float* W_n1 = (const float*)d_in[8];
    const float* b_n1 = (const float*)d_in[9];
    const float* W_n2 = (const float*)d_in[10];
    const float* b_n2 = (const float*)d_in[11];
    const float* W_c1 = (const float*)d_in[12];
    const float* b_c1 = (const float*)d_in[13];
    const float* W_c2 = (const float*)d_in[14];
    float* out = (float*)d_out;

    cudaFuncSetAttribute(edge_kernel,
                         cudaFuncAttributeMaxDynamicSharedMemorySize, SMEM_BYTES);

    zero_kernel<<<1024, 256>>>();
    count_kernel<<<(NEDGES + 255) / 256, 256>>>(edge_index);
    edge_kernel<<<dim3(NEDGES / EPB, NB), 128, SMEM_BYTES>>>(
        h, coord, edge_index, edge_attr,
        W_e1, b_e1, W_e2, b_e2, W_c1, b_c1, W_c2);
    node_kernel<<<dim3(NNODES / NPB, NB), 128>>>(
        h, coord, W_n1, b_n1, W_n2, b_n2, out);
}

// round 5
// speedup vs baseline: 1.2089x; 1.1568x over previous
#include <cuda_runtime.h>
#include <cstdint>

#define NB 2
#define NNODES 5000
#define NEDGES 160000
#define FIN 128
#define HID 128
#define ED 16
#define INE 288          // 2*FIN + 16 + ED
#define MT 32            // edges per block (tile M)
#define PAD_XS 292       // xs row stride (floats), 292 % 32 == 4 -> conflict-free A frags
#define PAD_H  132       // hidden row stride
#define NPB 8            // nodes per block (node kernel)

// ---------------- scratch (allocation-free) ----------------
__device__ float g_agg_h[NB * NNODES * HID];
__device__ float g_agg_c[NB * NNODES * 12];
__device__ float g_cnt[NNODES];
// tf32-rounded weights
__device__ float g_We1[INE * HID];
__device__ float g_We2[HID * HID];
__device__ float g_Wc1[HID * HID];

__device__ __forceinline__ float tf32r(float x) {
    uint32_t u;
    asm("cvt.rna.tf32.f32 %0, %1;" : "=r"(u) : "f"(x));
    return __uint_as_float(u);
}

__device__ __forceinline__ void mma_tf32(float c[4], uint32_t a0, uint32_t a1,
                                         uint32_t a2, uint32_t a3,
                                         uint32_t b0, uint32_t b1) {
    asm volatile(
        "mma.sync.aligned.m16n8k8.row.col.f32.tf32.tf32.f32 "
        "{%0,%1,%2,%3},{%4,%5,%6,%7},{%8,%9},{%0,%1,%2,%3};"
        : "+f"(c[0]), "+f"(c[1]), "+f"(c[2]), "+f"(c[3])
        : "r"(a0), "r"(a1), "r"(a2), "r"(a3), "r"(b0), "r"(b1));
}

// ---------------- helper kernels ----------------
__global__ void zero_kernel() {
    const int T1 = NB * NNODES * HID;
    const int T2 = T1 + NB * NNODES * 12;
    const int total = T2 + NNODES;
    for (int i = blockIdx.x * blockDim.x + threadIdx.x; i < total;
         i += gridDim.x * blockDim.x) {
        if (i < T1)       g_agg_h[i] = 0.0f;
        else if (i < T2)  g_agg_c[i - T1] = 0.0f;
        else              g_cnt[i - T2] = 0.0f;
    }
}

__global__ void count_kernel(const int* __restrict__ edge_index) {
    int e = blockIdx.x * blockDim.x + threadIdx.x;
    if (e < NEDGES) atomicAdd(&g_cnt[edge_index[e]], 1.0f);
}

__global__ void prep_kernel(const float* __restrict__ W_e1,
                            const float* __restrict__ W_e2,
                            const float* __restrict__ W_c1) {
    int i = blockIdx.x * blockDim.x + threadIdx.x;
    if (i < INE * HID) g_We1[i] = tf32r(W_e1[i]);
    if (i < HID * HID) {
        g_We2[i] = tf32r(W_e2[i]);
        g_Wc1[i] = tf32r(W_c1[i]);
    }
}

// ---------------- mma GEMM core: 16x32 tile per warp ----------------
// inS: smem [MT][PADIN] tf32-rounded; W: [K][HID] tf32-rounded; bias fp32.
template<int K, int PADIN>
__device__ __forceinline__ void mma_gemm(const float* __restrict__ inS,
                                         const float* __restrict__ W,
                                         const float* __restrict__ bias,
                                         int m_base, int n_base, int g, int tig,
                                         float c[4][4])
{
    #pragma unroll
    for (int j = 0; j < 4; j++) {
        float bv0 = bias[n_base + j * 8 + 2 * tig];
        float bv1 = bias[n_base + j * 8 + 2 * tig + 1];
        c[j][0] = bv0; c[j][1] = bv1; c[j][2] = bv0; c[j][3] = bv1;
    }
    #pragma unroll 2
    for (int k0 = 0; k0 < K; k0 += 8) {
        const float* xr = inS + (m_base + g) * PADIN + k0 + tig;
        uint32_t a0 = __float_as_uint(xr[0]);
        uint32_t a1 = __float_as_uint(xr[8 * PADIN]);
        uint32_t a2 = __float_as_uint(xr[4]);
        uint32_t a3 = __float_as_uint(xr[8 * PADIN + 4]);
        const float* wr = W + (k0 + tig) * HID + n_base + g;
        #pragma unroll
        for (int j = 0; j < 4; j++) {
            uint32_t b0 = __float_as_uint(wr[j * 8]);
            uint32_t b1 = __float_as_uint(wr[4 * HID + j * 8]);
            mma_tf32(c[j], a0, a1, a2, a3, b0, b1);
        }
    }
}

// smem float offsets
#define OFF_XS  0
#define OFF_B1  (MT * PAD_XS)
#define OFF_B2  (OFF_B1 + MT * PAD_H)
#define OFF_CDS (OFF_B2 + MT * PAD_H)
#define OFF_WS  (OFF_CDS + MT * 12)
#define OFF_IDX (OFF_WS + MT * 4)
#define SMEM_FLOATS (OFF_IDX + 2 * MT)
#define SMEM_BYTES  (SMEM_FLOATS * 4)

__global__ __launch_bounds__(256) void edge_kernel(
    const float* __restrict__ h, const float* __restrict__ coord,
    const int* __restrict__ edge_index, const float* __restrict__ edge_attr,
    const float* __restrict__ b_e1, const float* __restrict__ b_e2,
    const float* __restrict__ b_c1, const float* __restrict__ W_c2)
{
    extern __shared__ float sm[];
    float* xs   = sm + OFF_XS;    // [MT][PAD_XS]  GEMM1 input (tf32)
    float* buf1 = sm + OFF_B1;    // [MT][PAD_H]   h1 / h2
    float* buf2 = sm + OFF_B2;    // [MT][PAD_H]   ef (tf32)
    float* cds  = sm + OFF_CDS;   // [MT][12] fp32
    float* wsS  = sm + OFF_WS;    // [MT][4]  fp32
    int* rows_s = (int*)(sm + OFF_IDX);
    int* cols_s = rows_s + MT;

    const int t    = threadIdx.x;
    const int lane = t & 31;
    const int w    = t >> 5;
    const int g    = lane >> 2;   // group id
    const int tig  = lane & 3;    // thread in group
    const int m_base = (w >> 2) * 16;
    const int n_base = (w & 3) * 32;

    const int e0 = blockIdx.x * MT;
    const int b  = blockIdx.y;
    const float* hb = h + (size_t)b * NNODES * FIN;
    const float* cb = coord + (size_t)b * NNODES * 12;

    if (t < MT) {
        rows_s[t] = edge_index[e0 + t];
        cols_s[t] = edge_index[NEDGES + e0 + t];
    }
    __syncthreads();

    // gather h[row], h[col] (tf32-rounded) into xs rows [0..256)
    for (int i = t; i < MT * FIN; i += 256) {
        int e = i >> 7, k = i & 127;
        xs[e * PAD_XS + k]       = tf32r(hb[rows_s[e] * FIN + k]);
        xs[e * PAD_XS + 128 + k] = tf32r(hb[cols_s[e] * FIN + k]);
    }
    // edge_attr -> [272..288)
    for (int i = t; i < MT * ED; i += 256) {
        int e = i >> 4, c = i & 15;
        xs[e * PAD_XS + 2 * FIN + 16 + c] = tf32r(edge_attr[(size_t)(e0 + e) * ED + c]);
    }
    // coord diff (fp32, kept for scatter)
    for (int i = t; i < MT * 12; i += 256) {
        int e = i / 12, c = i % 12;
        cds[e * 12 + c] = cb[rows_s[e] * 12 + c] - cb[cols_s[e] * 12 + c];
    }
    __syncthreads();

    // radial -> xs rows [256..272)
    if (t < MT) {
        float cd[12];
        #pragma unroll
        for (int c = 0; c < 12; c++) cd[c] = cds[t * 12 + c];
        float prod[16], ss = 0.0f;
        #pragma unroll
        for (int j = 0; j < 4; j++)
            #pragma unroll
            for (int k = 0; k < 4; k++) {
                float p = cd[j*3]*cd[k*3] + cd[j*3+1]*cd[k*3+1] + cd[j*3+2]*cd[k*3+2];
                prod[j * 4 + k] = p;
                ss += p * p;
            }
        float inv = 1.0f / fmaxf(sqrtf(ss), 1e-12f);
        #pragma unroll
        for (int i = 0; i < 16; i++)
            xs[t * PAD_XS + 2 * FIN + i] = tf32r(prod[i] * inv);
    }
    __syncthreads();

    float c[4][4];

    // GEMM1: xs(288) @ We1 -> relu -> buf1 (tf32)
    mma_gemm<INE, PAD_XS>(xs, g_We1, b_e1, m_base, n_base, g, tig, c);
    #pragma unroll
    for (int j = 0; j < 4; j++) {
        int col = n_base + j * 8 + 2 * tig;
        buf1[(m_base + g)     * PAD_H + col]     = tf32r(fmaxf(c[j][0], 0.0f));
        buf1[(m_base + g)     * PAD_H + col + 1] = tf32r(fmaxf(c[j][1], 0.0f));
        buf1[(m_base + g + 8) * PAD_H + col]     = tf32r(fmaxf(c[j][2], 0.0f));
        buf1[(m_base + g + 8) * PAD_H + col + 1] = tf32r(fmaxf(c[j][3], 0.0f));
    }
    __syncthreads();

    // GEMM2: h1 @ We2 -> relu -> ef. Scatter agg_h directly from accums (fp32),
    // store tf32 copy in buf2 for GEMM3.
    mma_gemm<HID, PAD_H>(buf1, g_We2, b_e2, m_base, n_base, g, tig, c);
    {
        float* aggh = g_agg_h + (size_t)b * NNODES * HID;
        #pragma unroll
        for (int j = 0; j < 4; j++) {
            int col = n_base + j * 8 + 2 * tig;
            int eA = m_base + g, eB = m_base + g + 8;
            float v0 = fmaxf(c[j][0], 0.0f), v1 = fmaxf(c[j][1], 0.0f);
            float v2 = fmaxf(c[j][2], 0.0f), v3 = fmaxf(c[j][3], 0.0f);
            buf2[eA * PAD_H + col]     = tf32r(v0);
            buf2[eA * PAD_H + col + 1] = tf32r(v1);
            buf2[eB * PAD_H + col]     = tf32r(v2);
            buf2[eB * PAD_H + col + 1] = tf32r(v3);
            atomicAdd(&aggh[rows_s[eA] * HID + col],     v0);
            atomicAdd(&aggh[rows_s[eA] * HID + col + 1], v1);
            atomicAdd(&aggh[rows_s[eB] * HID + col],     v2);
            atomicAdd(&aggh[rows_s[eB] * HID + col + 1], v3);
        }
    }
    __syncthreads();

    // GEMM3: ef @ Wc1 -> relu -> buf1 (h2, tf32)
    mma_gemm<HID, PAD_H>(buf2, g_Wc1, b_c1, m_base, n_base, g, tig, c);
    #pragma unroll
    for (int j = 0; j < 4; j++) {
        int col = n_base + j * 8 + 2 * tig;
        buf1[(m_base + g)     * PAD_H + col]     = tf32r(fmaxf(c[j][0], 0.0f));
        buf1[(m_base + g)     * PAD_H + col + 1] = tf32r(fmaxf(c[j][1], 0.0f));
        buf1[(m_base + g + 8) * PAD_H + col]     = tf32r(fmaxf(c[j][2], 0.0f));
        buf1[(m_base + g + 8) * PAD_H + col + 1] = tf32r(fmaxf(c[j][3], 0.0f));
    }
    __syncthreads();

    // GEMM4 (scalar): w = h2 @ W_c2 [HID x 4]. 128 dots, 2 threads each.
    {
        int p = t >> 1, half = t & 1;
        int e = p >> 2, cc = p & 3;
        float a = 0.0f;
        int k0 = half * 64;
        #pragma unroll 8
        for (int k = k0; k < k0 + 64; k++)
            a = fmaf(buf1[e * PAD_H + k], W_c2[k * 4 + cc], a);
        a += __shfl_xor_sync(0xffffffffu, a, 1);
        if (half == 0) wsS[e * 4 + cc] = a;
    }
    __syncthreads();

    // coord scatter: agg_c += cd * w
    float* aggc = g_agg_c + (size_t)b * NNODES * 12;
    for (int i = t; i < MT * 12; i += 256) {
        int e = i / 12, cc = i % 12;
        atomicAdd(&aggc[rows_s[e] * 12 + cc], cds[e * 12 + cc] * wsS[e * 4 + cc / 3]);
    }
}

// ---------------- node MLP (fp32 scalar) + coord update ----------------
__global__ __launch_bounds__(128) void node_kernel(
    const float* __restrict__ h, const float* __restrict__ coord,
    const float* __restrict__ W_n1, const float* __restrict__ b_n1,
    const float* __restrict__ W_n2, const float* __restrict__ b_n2,
    float* __restrict__ out)
{
    __shared__ float zs[NPB][2 * FIN];
    __shared__ float h1s[NPB][HID];

    const int t  = threadIdx.x;
    const int n0 = blockIdx.x * NPB;
    const int b  = blockIdx.y;
    const float* hb   = h + (size_t)b * NNODES * FIN;
    const float* aggh = g_agg_h + (size_t)b * NNODES * HID;

    #pragma unroll
    for (int e = 0; e < NPB; e++) {
        zs[e][t]       = hb[(n0 + e) * FIN + t];
        zs[e][FIN + t] = aggh[(n0 + e) * HID + t];
    }
    __syncthreads();

    float acc[NPB];
    {
        float bj = b_n1[t];
        #pragma unroll
        for (int e = 0; e < NPB; e++) acc[e] = bj;
        for (int k = 0; k < 2 * FIN; k += 4) {
            float w0 = W_n1[(k + 0) * HID + t];
            float w1 = W_n1[(k + 1) * HID + t];
            float w2 = W_n1[(k + 2) * HID + t];
            float w3 = W_n1[(k + 3) * HID + t];
            #pragma unroll
            for (int e = 0; e < NPB; e++) {
                float4 x4 = *(const float4*)&zs[e][k];
                acc[e] = fmaf(x4.x, w0, fmaf(x4.y, w1, fmaf(x4.z, w2, fmaf(x4.w, w3, acc[e]))));
            }
        }
        #pragma unroll
        for (int e = 0; e < NPB; e++) h1s[e][t] = fmaxf(acc[e], 0.0f);
    }
    __syncthreads();
    {
        float bj = b_n2[t];
        #pragma unroll
        for (int e = 0; e < NPB; e++) acc[e] = bj;
        for (int k = 0; k < HID; k += 4) {
            float w0 = W_n2[(k + 0) * FIN + t];
            float w1 = W_n2[(k + 1) * FIN + t];
            float w2 = W_n2[(k + 2) * FIN + t];
            float w3 = W_n2[(k + 3) * FIN + t];
            #pragma unroll
            for (int e = 0; e < NPB; e++) {
                float4 x4 = *(const float4*)&h1s[e][k];
                acc[e] = fmaf(x4.x, w0, fmaf(x4.y, w1, fmaf(x4.z, w2, fmaf(x4.w, w3, acc[e]))));
            }
        }
    }

    float* outh = out + (size_t)b * NNODES * FIN;
    #pragma unroll
    for (int e = 0; e < NPB; e++)
        outh[(n0 + e) * FIN + t] = zs[e][t] + acc[e];

    float* outc = out + (size_t)NB * NNODES * FIN + (size_t)b * NNODES * 12;
    const float* cb   = coord + (size_t)b * NNODES * 12;
    const float* aggc = g_agg_c + (size_t)b * NNODES * 12;
    for (int i = t; i < NPB * 12; i += 128) {
        int e = i / 12, cc = i % 12;
        int n = n0 + e;
        float cnt = fmaxf(g_cnt[n], 1.0f);
        outc[n * 12 + cc] = cb[n * 12 + cc] + aggc[n * 12 + cc] / cnt;
    }
}

extern "C" void kernel_launch(void* const* d_in, const int* in_sizes, int n_in,
                              void* d_out, int out_size)
{
    const float* h         = (const float*)d_in[0];
    const float* coord     = (const float*)d_in[1];
    const int*   edge_index= (const int*)  d_in[2];
    const float* edge_attr = (const float*)d_in[3];
    const float* W_e1 = (const float*)d_in[4];
    const float* b_e1 = (const float*)d_in[5];
    const float* W_e2 = (const float*)d_in[6];
    const float* b_e2 = (const float*)d_in[7];
    const float* W_n1 = (const float*)d_in[8];
    const float* b_n1 = (const float*)d_in[9];
    const float* W_n2 = (const float*)d_in[10];
    const float* b_n2 = (const float*)d_in[11];
    const float* W_c1 = (const float*)d_in[12];
    const float* b_c1 = (const float*)d_in[13];
    const float* W_c2 = (const float*)d_in[14];
    float* out = (float*)d_out;

    cudaFuncSetAttribute(edge_kernel,
                         cudaFuncAttributeMaxDynamicSharedMemorySize, SMEM_BYTES);

    prep_kernel<<<(INE * HID + 255) / 256, 256>>>(W_e1, W_e2, W_c1);
    zero_kernel<<<1024, 256>>>();
    count_kernel<<<(NEDGES + 255) / 256, 256>>>(edge_index);
    edge_kernel<<<dim3(NEDGES / MT, NB), 256, SMEM_BYTES>>>(
        h, coord, edge_index, edge_attr, b_e1, b_e2, b_c1, W_c2);
    node_kernel<<<dim3(NNODES / NPB, NB), 128>>>(
        h, coord, W_n1, b_n1, W_n2, b_n2, out);
}

// round 6
// speedup vs baseline: 2.1042x; 1.7405x over previous
#include <cuda_runtime.h>
#include <cstdint>

#define NB 2
#define NNODES 5000
#define NEDGES 160000
#define FIN 128
#define HID 128
#define ED 16
#define INE 288          // 2*FIN + 16 + ED
#define MT 64            // edges per block
#define PAD_XS 292       // 292 % 32 == 4 -> conflict-free A frags
#define PAD_H  132       // 132 % 32 == 4
#define NPB 8

// ---------------- scratch (allocation-free) ----------------
__device__ float g_agg_h[NB * NNODES * HID];
__device__ float g_agg_c[NB * NNODES * 12];
__device__ float g_cnt[NNODES];
__device__ float g_We1[INE * HID];
__device__ float g_We2[HID * HID];
__device__ float g_Wc1[HID * HID];

__device__ __forceinline__ float tf32r(float x) {
    uint32_t u;
    asm("cvt.rna.tf32.f32 %0, %1;" : "=r"(u) : "f"(x));
    return __uint_as_float(u);
}

__device__ __forceinline__ void mma_tf32(float c[4], uint32_t a0, uint32_t a1,
                                         uint32_t a2, uint32_t a3,
                                         uint32_t b0, uint32_t b1) {
    asm volatile(
        "mma.sync.aligned.m16n8k8.row.col.f32.tf32.tf32.f32 "
        "{%0,%1,%2,%3},{%4,%5,%6,%7},{%8,%9},{%0,%1,%2,%3};"
        : "+f"(c[0]), "+f"(c[1]), "+f"(c[2]), "+f"(c[3])
        : "r"(a0), "r"(a1), "r"(a2), "r"(a3), "r"(b0), "r"(b1));
}

// ---------------- helper kernels ----------------
__global__ void zero_kernel() {
    const int T1 = NB * NNODES * HID;
    const int T2 = T1 + NB * NNODES * 12;
    const int total = T2 + NNODES;
    for (int i = blockIdx.x * blockDim.x + threadIdx.x; i < total;
         i += gridDim.x * blockDim.x) {
        if (i < T1)       g_agg_h[i] = 0.0f;
        else if (i < T2)  g_agg_c[i - T1] = 0.0f;
        else              g_cnt[i - T2] = 0.0f;
    }
}

__global__ void count_kernel(const int* __restrict__ edge_index) {
    int e = blockIdx.x * blockDim.x + threadIdx.x;
    if (e < NEDGES) atomicAdd(&g_cnt[edge_index[e]], 1.0f);
}

__global__ void prep_kernel(const float* __restrict__ W_e1,
                            const float* __restrict__ W_e2,
                            const float* __restrict__ W_c1) {
    int i = blockIdx.x * blockDim.x + threadIdx.x;
    if (i < INE * HID) g_We1[i] = tf32r(W_e1[i]);
    if (i < HID * HID) {
        g_We2[i] = tf32r(W_e2[i]);
        g_Wc1[i] = tf32r(W_c1[i]);
    }
}

// ---------------- mma GEMM: 32x32 warp tile, B direct from global ----------------
// c[mi][nj][4] accumulators. 16 independent mmas per k-step.
template<int K, int PADIN>
__device__ __forceinline__ void mma_gemm(const float* __restrict__ inS,
                                         const float* __restrict__ Wg,
                                         const float* __restrict__ bias,
                                         int m_base, int n_base, int g, int tig,
                                         float c[2][4][4])
{
    #pragma unroll
    for (int nj = 0; nj < 4; nj++) {
        float bv0 = bias[n_base + nj * 8 + 2 * tig];
        float bv1 = bias[n_base + nj * 8 + 2 * tig + 1];
        #pragma unroll
        for (int mi = 0; mi < 2; mi++) {
            c[mi][nj][0] = bv0; c[mi][nj][1] = bv1;
            c[mi][nj][2] = bv0; c[mi][nj][3] = bv1;
        }
    }
    #pragma unroll 4
    for (int k0 = 0; k0 < K; k0 += 8) {
        uint32_t a[2][4];
        #pragma unroll
        for (int mi = 0; mi < 2; mi++) {
            const float* xr = inS + (m_base + mi * 16 + g) * PADIN + k0 + tig;
            a[mi][0] = __float_as_uint(xr[0]);
            a[mi][1] = __float_as_uint(xr[8 * PADIN]);
            a[mi][2] = __float_as_uint(xr[4]);
            a[mi][3] = __float_as_uint(xr[8 * PADIN + 4]);
        }
        const float* wr = Wg + (k0 + tig) * HID + n_base + g;
        uint32_t b0[4], b1[4];
        #pragma unroll
        for (int nj = 0; nj < 4; nj++) {
            b0[nj] = __float_as_uint(wr[nj * 8]);
            b1[nj] = __float_as_uint(wr[4 * HID + nj * 8]);
        }
        #pragma unroll
        for (int nj = 0; nj < 4; nj++)
            #pragma unroll
            for (int mi = 0; mi < 2; mi++)
                mma_tf32(c[mi][nj], a[mi][0], a[mi][1], a[mi][2], a[mi][3],
                         b0[nj], b1[nj]);
    }
}

// smem float offsets
#define OFF_XS  0
#define OFF_EF  OFF_XS                       // alias (xs dead after GEMM1)
#define OFF_H2  (OFF_XS + MT * PAD_H)        // alias, second half of xs region
#define OFF_B1  (MT * PAD_XS)                // h1
#define OFF_CDS (OFF_B1 + MT * PAD_H)
#define OFF_WS  (OFF_CDS + MT * 12)
#define OFF_IDX (OFF_WS + MT * 4)
#define SMEM_FLOATS (OFF_IDX + 2 * MT)
#define SMEM_BYTES  (SMEM_FLOATS * 4)

__global__ __launch_bounds__(256, 2) void edge_kernel(
    const float* __restrict__ h, const float* __restrict__ coord,
    const int* __restrict__ edge_index, const float* __restrict__ edge_attr,
    const float* __restrict__ b_e1, const float* __restrict__ b_e2,
    const float* __restrict__ b_c1, const float* __restrict__ W_c2)
{
    extern __shared__ float sm[];
    float* xs   = sm + OFF_XS;    // [MT][PAD_XS] GEMM1 input
    float* efS  = sm + OFF_EF;    // [MT][PAD_H]
    float* h2S  = sm + OFF_H2;    // [MT][PAD_H]
    float* h1S  = sm + OFF_B1;    // [MT][PAD_H]
    float* cds  = sm + OFF_CDS;
    float* wsS  = sm + OFF_WS;
    int* rows_s = (int*)(sm + OFF_IDX);
    int* cols_s = rows_s + MT;

    const int t    = threadIdx.x;
    const int lane = t & 31;
    const int w    = t >> 5;
    const int g    = lane >> 2;
    const int tig  = lane & 3;
    const int m_base = (w >> 2) * 32;   // 2 m-warps
    const int n_base = (w & 3) * 32;    // 4 n-warps

    const int e0 = blockIdx.x * MT;
    const int b  = blockIdx.y;
    const float* hb = h + (size_t)b * NNODES * FIN;
    const float* cb = coord + (size_t)b * NNODES * 12;

    if (t < MT) {
        rows_s[t] = edge_index[e0 + t];
        cols_s[t] = edge_index[NEDGES + e0 + t];
    }
    __syncthreads();

    // gather h[row], h[col] (tf32-rounded)
    for (int i = t; i < MT * FIN; i += 256) {
        int e = i >> 7, k = i & 127;
        xs[e * PAD_XS + k]       = tf32r(hb[rows_s[e] * FIN + k]);
        xs[e * PAD_XS + 128 + k] = tf32r(hb[cols_s[e] * FIN + k]);
    }
    for (int i = t; i < MT * ED; i += 256) {
        int e = i >> 4, c = i & 15;
        xs[e * PAD_XS + 2 * FIN + 16 + c] = tf32r(edge_attr[(size_t)(e0 + e) * ED + c]);
    }
    for (int i = t; i < MT * 12; i += 256) {
        int e = i / 12, c = i % 12;
        cds[e * 12 + c] = cb[rows_s[e] * 12 + c] - cb[cols_s[e] * 12 + c];
    }
    __syncthreads();

    // radial
    if (t < MT) {
        float cd[12];
        #pragma unroll
        for (int c = 0; c < 12; c++) cd[c] = cds[t * 12 + c];
        float prod[16], ss = 0.0f;
        #pragma unroll
        for (int j = 0; j < 4; j++)
            #pragma unroll
            for (int k = 0; k < 4; k++) {
                float p = cd[j*3]*cd[k*3] + cd[j*3+1]*cd[k*3+1] + cd[j*3+2]*cd[k*3+2];
                prod[j * 4 + k] = p;
                ss += p * p;
            }
        float inv = 1.0f / fmaxf(sqrtf(ss), 1e-12f);
        #pragma unroll
        for (int i = 0; i < 16; i++)
            xs[t * PAD_XS + 2 * FIN + i] = tf32r(prod[i] * inv);
    }
    __syncthreads();

    float c[2][4][4];

    // GEMM1: xs(288) @ We1 -> relu -> h1
    mma_gemm<INE, PAD_XS>(xs, g_We1, b_e1, m_base, n_base, g, tig, c);
    #pragma unroll
    for (int nj = 0; nj < 4; nj++) {
        int col = n_base + nj * 8 + 2 * tig;
        #pragma unroll
        for (int mi = 0; mi < 2; mi++) {
            int r = m_base + mi * 16 + g;
            h1S[r * PAD_H + col]           = tf32r(fmaxf(c[mi][nj][0], 0.0f));
            h1S[r * PAD_H + col + 1]       = tf32r(fmaxf(c[mi][nj][1], 0.0f));
            h1S[(r + 8) * PAD_H + col]     = tf32r(fmaxf(c[mi][nj][2], 0.0f));
            h1S[(r + 8) * PAD_H + col + 1] = tf32r(fmaxf(c[mi][nj][3], 0.0f));
        }
    }
    __syncthreads();

    // GEMM2: h1 @ We2 -> relu -> ef ; scatter agg_h in fp32 from accums
    mma_gemm<HID, PAD_H>(h1S, g_We2, b_e2, m_base, n_base, g, tig, c);
    {
        float* aggh = g_agg_h + (size_t)b * NNODES * HID;
        #pragma unroll
        for (int nj = 0; nj < 4; nj++) {
            int col = n_base + nj * 8 + 2 * tig;
            #pragma unroll
            for (int mi = 0; mi < 2; mi++) {
                int r = m_base + mi * 16 + g;
                float v0 = fmaxf(c[mi][nj][0], 0.0f), v1 = fmaxf(c[mi][nj][1], 0.0f);
                float v2 = fmaxf(c[mi][nj][2], 0.0f), v3 = fmaxf(c[mi][nj][3], 0.0f);
                efS[r * PAD_H + col]           = tf32r(v0);
                efS[r * PAD_H + col + 1]       = tf32r(v1);
                efS[(r + 8) * PAD_H + col]     = tf32r(v2);
                efS[(r + 8) * PAD_H + col + 1] = tf32r(v3);
                atomicAdd(&aggh[rows_s[r] * HID + col],           v0);
                atomicAdd(&aggh[rows_s[r] * HID + col + 1],       v1);
                atomicAdd(&aggh[rows_s[r + 8] * HID + col],       v2);
                atomicAdd(&aggh[rows_s[r + 8] * HID + col + 1],   v3);
            }
        }
    }
    __syncthreads();

    // GEMM3: ef @ Wc1 -> relu -> h2
    mma_gemm<HID, PAD_H>(efS, g_Wc1, b_c1, m_base, n_base, g, tig, c);
    #pragma unroll
    for (int nj = 0; nj < 4; nj++) {
        int col = n_base + nj * 8 + 2 * tig;
        #pragma unroll
        for (int mi = 0; mi < 2; mi++) {
            int r = m_base + mi * 16 + g;
            h2S[r * PAD_H + col]           = fmaxf(c[mi][nj][0], 0.0f);
            h2S[r * PAD_H + col + 1]       = fmaxf(c[mi][nj][1], 0.0f);
            h2S[(r + 8) * PAD_H + col]     = fmaxf(c[mi][nj][2], 0.0f);
            h2S[(r + 8) * PAD_H + col + 1] = fmaxf(c[mi][nj][3], 0.0f);
        }
    }
    __syncthreads();

    // GEMM4 (scalar): w = h2 @ W_c2 [HID x 4]; one dot per thread
    {
        int e = t >> 2, cc = t & 3;
        float a = 0.0f;
        #pragma unroll 8
        for (int k = 0; k < HID; k++)
            a = fmaf(h2S[e * PAD_H + k], W_c2[k * 4 + cc], a);
        wsS[e * 4 + cc] = a;
    }
    __syncthreads();

    // coord scatter
    float* aggc = g_agg_c + (size_t)b * NNODES * 12;
    for (int i = t; i < MT * 12; i += 256) {
        int e = i / 12, cc = i % 12;
        atomicAdd(&aggc[rows_s[e] * 12 + cc], cds[e * 12 + cc] * wsS[e * 4 + cc / 3]);
    }
}

// ---------------- node MLP (fp32 scalar) + coord update ----------------
__global__ __launch_bounds__(128) void node_kernel(
    const float* __restrict__ h, const float* __restrict__ coord,
    const float* __restrict__ W_n1, const float* __restrict__ b_n1,
    const float* __restrict__ W_n2, const float* __restrict__ b_n2,
    float* __restrict__ out)
{
    __shared__ float zs[NPB][2 * FIN];
    __shared__ float h1s[NPB][HID];

    const int t  = threadIdx.x;
    const int n0 = blockIdx.x * NPB;
    const int b  = blockIdx.y;
    const float* hb   = h + (size_t)b * NNODES * FIN;
    const float* aggh = g_agg_h + (size_t)b * NNODES * HID;

    #pragma unroll
    for (int e = 0; e < NPB; e++) {
        zs[e][t]       = hb[(n0 + e) * FIN + t];
        zs[e][FIN + t] = aggh[(n0 + e) * HID + t];
    }
    __syncthreads();

    float acc[NPB];
    {
        float bj = b_n1[t];
        #pragma unroll
        for (int e = 0; e < NPB; e++) acc[e] = bj;
        for (int k = 0; k < 2 * FIN; k += 4) {
            float w0 = W_n1[(k + 0) * HID + t];
            float w1 = W_n1[(k + 1) * HID + t];
            float w2 = W_n1[(k + 2) * HID + t];
            float w3 = W_n1[(k + 3) * HID + t];
            #pragma unroll
            for (int e = 0; e < NPB; e++) {
                float4 x4 = *(const float4*)&zs[e][k];
                acc[e] = fmaf(x4.x, w0, fmaf(x4.y, w1, fmaf(x4.z, w2, fmaf(x4.w, w3, acc[e]))));
            }
        }
        #pragma unroll
        for (int e = 0; e < NPB; e++) h1s[e][t] = fmaxf(acc[e], 0.0f);
    }
    __syncthreads();
    {
        float bj = b_n2[t];
        #pragma unroll
        for (int e = 0; e < NPB; e++) acc[e] = bj;
        for (int k = 0; k < HID; k += 4) {
            float w0 = W_n2[(k + 0) * FIN + t];
            float w1 = W_n2[(k + 1) * FIN + t];
            float w2 = W_n2[(k + 2) * FIN + t];
            float w3 = W_n2[(k + 3) * FIN + t];
            #pragma unroll
            for (int e = 0; e < NPB; e++) {
                float4 x4 = *(const float4*)&h1s[e][k];
                acc[e] = fmaf(x4.x, w0, fmaf(x4.y, w1, fmaf(x4.z, w2, fmaf(x4.w, w3, acc[e]))));
            }
        }
    }

    float* outh = out + (size_t)b * NNODES * FIN;
    #pragma unroll
    for (int e = 0; e < NPB; e++)
        outh[(n0 + e) * FIN + t] = zs[e][t] + acc[e];

    float* outc = out + (size_t)NB * NNODES * FIN + (size_t)b * NNODES * 12;
    const float* cb   = coord + (size_t)b * NNODES * 12;
    const float* aggc = g_agg_c + (size_t)b * NNODES * 12;
    for (int i = t; i < NPB * 12; i += 128) {
        int e = i / 12, cc = i % 12;
        int n = n0 + e;
        float cnt = fmaxf(g_cnt[n], 1.0f);
        outc[n * 12 + cc] = cb[n * 12 + cc] + aggc[n * 12 + cc] / cnt;
    }
}

extern "C" void kernel_launch(void* const* d_in, const int* in_sizes, int n_in,
                              void* d_out, int out_size)
{
    const float* h         = (const float*)d_in[0];
    const float* coord     = (const float*)d_in[1];
    const int*   edge_index= (const int*)  d_in[2];
    const float* edge_attr = (const float*)d_in[3];
    const float* W_e1 = (const float*)d_in[4];
    const float* b_e1 = (const float*)d_in[5];
    const float* W_e2 = (const float*)d_in[6];
    const float* b_e2 = (const float*)d_in[7];
    const float* W_n1 = (const float*)d_in[8];
    const float* b_n1 = (const float*)d_in[9];
    const float* W_n2 = (const float*)d_in[10];
    const float* b_n2 = (const float*)d_in[11];
    const float* W_c1 = (const float*)d_in[12];
    const float* b_c1 = (const float*)d_in[13];
    const float* W_c2 = (const float*)d_in[14];
    float* out = (float*)d_out;

    cudaFuncSetAttribute(edge_kernel,
                         cudaFuncAttributeMaxDynamicSharedMemorySize, SMEM_BYTES);

    prep_kernel<<<(INE * HID + 255) / 256, 256>>>(W_e1, W_e2, W_c1);
    zero_kernel<<<1024, 256>>>();
    count_kernel<<<(NEDGES + 255) / 256, 256>>>(edge_index);
    edge_kernel<<<dim3(NEDGES / MT, NB), 256, SMEM_BYTES>>>(
        h, coord, edge_index, edge_attr, b_e1, b_e2, b_c1, W_c2);
    node_kernel<<<dim3(NNODES / NPB, NB), 128>>>(
        h, coord, W_n1, b_n1, W_n2, b_n2, out);
}